// round 11
// baseline (speedup 1.0000x reference)
#include <cuda_runtime.h>
#include <math.h>

#define B 8
#define M 12
#define NN 32
#define D 256
#define C 1024      // N*N
#define CH 512      // C/R
#define BM 96

typedef unsigned long long ull;

// Scratch (allocation-free rule: device globals). No flags/counters needed.
__device__ float g_S[BM * NN];    // row sums per bm
__device__ float g_U[NN * CH];    // [n][o] collapsed-GEMM1 weights
__device__ float g_cov[BM * C];   // centered cov (sign -> mask)
__device__ float g_ev[BM * C];    // exp(sigmoid(e2)), pre-mask

// ---- packed f32x2 helpers -------------------------------------------------
__device__ __forceinline__ ull ffma2(ull a, ull b, ull c) {
    ull d_;
    asm("fma.rn.f32x2 %0, %1, %2, %3;" : "=l"(d_) : "l"(a), "l"(b), "l"(c));
    return d_;
}
__device__ __forceinline__ ull pk2(float lo, float hi) {
    ull r;
    asm("mov.b64 %0, {%1, %2};" : "=l"(r) : "f"(lo), "f"(hi));
    return r;
}
__device__ __forceinline__ float unpk_add(ull v) {
    float lo, hi;
    asm("mov.b64 {%0, %1}, %2;" : "=f"(lo), "=f"(hi) : "l"(v));
    return lo + hi;
}
__device__ __forceinline__ void unpk2(ull v, float& lo, float& hi) {
    asm("mov.b64 {%0, %1}, %2;" : "=f"(lo), "=f"(hi) : "l"(v));
}

// smem swizzle: q in [0,128) float4 units within a 512-float row
#define SWZ(q) (((q) & 0x70) | (((q) ^ ((q) >> 4)) & 0x0F))
// scalar-float swizzled offset for element o in a 512-float row
#define SWZ4(o) (SWZ((o) >> 2) * 4 + ((o) & 3))

#define XPAD 260   // floats per padded x row (= 65 float4)

// ---------------------------------------------------------------------------
// kSU: grid 112. blocks [0,16): U[n][o] = rowsum+2*colsum-diag of W1 row o.
//                blocks [16,112): S row sums for bm = bid-16.
// Fully independent halves — no waits.
// ---------------------------------------------------------------------------
__global__ void __launch_bounds__(256) kSU(const float* __restrict__ x,
                                           const float* __restrict__ W1) {
    extern __shared__ float sm[];
    const int tid = threadIdx.x;
    const int w = tid >> 5, lane = tid & 31;

    if (blockIdx.x < 16) {
        const int ub = blockIdx.x;
        float* smT = sm + w * 1056;   // per-warp 33x32 transpose buf
        #pragma unroll
        for (int i = 0; i < 4; i++) {
            const int o = ub * 32 + w * 4 + i;
            const float* row = W1 + (size_t)o * C;
            float r[32], cs = 0.f;
            #pragma unroll
            for (int j = 0; j < 32; j++) { r[j] = row[j * 32 + lane]; cs += r[j]; }
            #pragma unroll
            for (int j = 0; j < 32; j++) smT[j * 33 + lane] = r[j];
            __syncwarp();
            float rs = 0.f;
            #pragma unroll
            for (int mm = 0; mm < 32; mm++) rs += smT[lane * 33 + mm];
            const float dg = smT[lane * 33 + lane];
            g_U[lane * CH + o] = rs + 2.f * cs - dg;   // lane = n
            __syncwarp();
        }
        return;
    }

    // S blocks: bm = bid-16; thread (n = tid>>3, j = tid&7)
    const int bm = blockIdx.x - 16;
    const int n = tid >> 3, j = tid & 7;
    const float4* xr = (const float4*)(x + (size_t)bm * (NN * D) + n * D);
    float s = 0.f;
    #pragma unroll
    for (int t = 0; t < 8; t++) {            // j + 8t: coalesced within row
        const float4 v = xr[j + 8 * t];
        s += (v.x + v.y) + (v.z + v.w);
    }
    s += __shfl_xor_sync(0xffffffffu, s, 4);
    s += __shfl_xor_sync(0xffffffffu, s, 2);
    s += __shfl_xor_sync(0xffffffffu, s, 1);
    if (j == 0) g_S[bm * NN + n] = s;
}

// ---------------------------------------------------------------------------
// kMid: grid 320. No waits anywhere.
//  blocks [0,192):   cov halves: bm = bid>>1, rows [half*16, half*16+16).
//                    S LOADED from g_S (no rowsum stage).
//  blocks [192,320): e2 for (ct = idx>>3 in 0..15, b = idx&7): h computed
//                    inline from g_U/g_S, two-pass smem-staged W2 GEMM
//                    (32 rows per pass), writes exp(sigmoid(e2)) to g_ev.
// ---------------------------------------------------------------------------
__global__ void __launch_bounds__(256, 2) kMid(const float* __restrict__ x,
                                               const float* __restrict__ W2) {
    extern __shared__ float sm[];
    const int tid = threadIdx.x;
    const int w = tid >> 5, lane = tid & 31;

    if (blockIdx.x < 192) {
        // ---- cov half blocks ----
        const int bm = blockIdx.x >> 1;
        const int half = blockIdx.x & 1;
        const int n0 = half * 16;
        float* xs  = sm;                 // padded natural [n*XPAD + d], 8320
        float* red = sm + 8320;          // 8 warps x 512
        float* S   = sm + 8320 + 4096;   // 32

        if (tid < 32) S[tid] = g_S[bm * NN + tid];

        const float4* xg4 = (const float4*)(x + (size_t)bm * (NN * D));
        float4* xs4 = (float4*)xs;
        #pragma unroll
        for (int t = 0; t < 8; t++) {
            const int i = tid + t * 256;
            const int n = i >> 6, q = i & 63;
            xs4[n * 65 + q] = xg4[i];    // conflict-free STS.128
        }
        __syncthreads();

        // register fill: xk = x[k=lane][w*32 .. w*32+31]
        ull xk2[16];
        const float* xrow = xs + lane * XPAD + w * 32;
        #pragma unroll
        for (int jj = 0; jj < 16; jj++) xk2[jj] = *(const ull*)(xrow + 2 * jj);

        ull acc2[16];
        #pragma unroll
        for (int nn = 0; nn < 16; nn++) acc2[nn] = 0ull;

        const ulonglong2* xs2 = (const ulonglong2*)xs;   // rows stride 65 f4
        #pragma unroll
        for (int nn = 0; nn < 16; nn++) {
            const ulonglong2* rowp = xs2 + (n0 + nn) * 65 + w * 8;
            #pragma unroll
            for (int jj = 0; jj < 8; jj++) {
                const ulonglong2 bv = rowp[jj];          // broadcast LDS.128
                acc2[nn] = ffma2(bv.x, xk2[2 * jj], acc2[nn]);
                acc2[nn] = ffma2(bv.y, xk2[2 * jj + 1], acc2[nn]);
            }
        }

        #pragma unroll
        for (int nn = 0; nn < 16; nn++)
            red[w * 512 + nn * 32 + lane] = unpk_add(acc2[nn]);
        __syncthreads();

        if (tid < 128) {
            const float4* red4 = (const float4*)red;
            float4 cv = make_float4(0.f, 0.f, 0.f, 0.f);
            #pragma unroll
            for (int ww = 0; ww < 8; ww++) {
                const float4 t = red4[ww * 128 + tid];
                cv.x += t.x; cv.y += t.y; cv.z += t.z; cv.w += t.w;
            }
            const int n = n0 + (tid >> 3), k0 = (tid & 7) * 4;
            const float sn = S[n] * (1.f / 256.f);
            cv.x -= sn * S[k0 + 0]; cv.y -= sn * S[k0 + 1];
            cv.z -= sn * S[k0 + 2]; cv.w -= sn * S[k0 + 3];
            ((float4*)(g_cov + (size_t)bm * C + n0 * NN))[tid] = cv;
        }
        return;
    }

    // ---- e2 blocks ----
    const int idx = blockIdx.x - 192;
    const int ct = idx >> 3, b = idx & 7;
    float* W2s  = sm;                    // 16384 floats (32-row pass)
    float* hs   = sm + 16384;            // 12 x 512 swizzled
    float* S12t = sm + 16384 + 6144;     // [n*12 + m], 384

    const float4* w2g = (const float4*)(W2 + (size_t)(ct * 64) * CH);

    // stage W2 pass 0 (rows ct*64 .. +32) swizzled
    #pragma unroll
    for (int t = 0; t < 16; t++) {
        const int i = tid + t * 256;
        const int r = i >> 7, q = i & 127;
        ((float4*)W2s)[r * 128 + SWZ(q)] = w2g[i];
    }
    // S transposed: S12t[n*12+m]
    for (int i = tid; i < 384; i += 256) {
        const int m = i >> 5, n = i & 31;
        S12t[n * 12 + m] = g_S[(b * M + m) * NN + n];
    }
    __syncthreads();

    // h inline: thread owns o0 = tid, o1 = tid+256; pairs over m
    {
        ull hacc[12];
        #pragma unroll
        for (int mm = 0; mm < 12; mm++) hacc[mm] = 0ull;
        #pragma unroll 4
        for (int n = 0; n < 32; n++) {
            const float u0 = g_U[n * CH + tid];
            const float u1 = g_U[n * CH + tid + 256];
            const ull u00 = pk2(u0, u0), u11 = pk2(u1, u1);
            #pragma unroll
            for (int mm = 0; mm < 6; mm++) {
                const ull sv = *(const ull*)(S12t + n * 12 + 2 * mm);
                hacc[mm]     = ffma2(sv, u00, hacc[mm]);
                hacc[6 + mm] = ffma2(sv, u11, hacc[6 + mm]);
            }
        }
        const int so0 = SWZ4(tid), so1 = SWZ4(tid + 256) - 2048;  // within-row offsets
        #pragma unroll
        for (int mm = 0; mm < 6; mm++) {
            float a, bb;
            unpk2(hacc[mm], a, bb);
            hs[(2 * mm) * 512 + so0]     = fmaxf(a  * (1.f / 512.f), 0.f);
            hs[(2 * mm + 1) * 512 + so0] = fmaxf(bb * (1.f / 512.f), 0.f);
            unpk2(hacc[6 + mm], a, bb);
            hs[(2 * mm) * 512 + 2048 + so1]     = fmaxf(a  * (1.f / 512.f), 0.f);
            hs[(2 * mm + 1) * 512 + 2048 + so1] = fmaxf(bb * (1.f / 512.f), 0.f);
        }
    }
    __syncthreads();

    const int c2 = tid >> 3;          // row within pass (0..31)
    const int kc = tid & 7;           // k-chunk of 64 floats
    const int kc16 = kc * 16;
    const ulonglong2* hu = (const ulonglong2*)hs;
    const ulonglong2* Wu = (const ulonglong2*)W2s;

    ull acc0[12], acc1[12];
    #pragma unroll
    for (int m = 0; m < 12; m++) { acc0[m] = 0ull; acc1[m] = 0ull; }

    // GEMM pass 0
    #pragma unroll 4
    for (int j = 0; j < 16; j++) {
        const int qs = kc16 + ((j ^ kc) & 15);
        const ulonglong2 wv = Wu[c2 * 128 + qs];
        #pragma unroll
        for (int m = 0; m < 12; m++) {
            const ulonglong2 hv = hu[m * 128 + qs];
            acc0[m] = ffma2(wv.x, hv.x, acc0[m]);
            acc0[m] = ffma2(wv.y, hv.y, acc0[m]);
        }
    }
    __syncthreads();
    // stage W2 pass 1 (rows +32 .. +64)
    #pragma unroll
    for (int t = 0; t < 16; t++) {
        const int i = tid + t * 256;
        const int r = i >> 7, q = i & 127;
        ((float4*)W2s)[r * 128 + SWZ(q)] = w2g[4096 + i];
    }
    __syncthreads();
    // GEMM pass 1
    #pragma unroll 4
    for (int j = 0; j < 16; j++) {
        const int qs = kc16 + ((j ^ kc) & 15);
        const ulonglong2 wv = Wu[c2 * 128 + qs];
        #pragma unroll
        for (int m = 0; m < 12; m++) {
            const ulonglong2 hv = hu[m * 128 + qs];
            acc1[m] = ffma2(wv.x, hv.x, acc1[m]);
            acc1[m] = ffma2(wv.y, hv.y, acc1[m]);
        }
    }
    __syncthreads();   // done with W2s; reuse as partials

    float* part = W2s;   // [kc][row*12+m], row in 0..63, stride 771
    #pragma unroll
    for (int m = 0; m < 12; m++) {
        part[kc * 771 + c2 * 12 + m]        = unpk_add(acc0[m]);
        part[kc * 771 + (32 + c2) * 12 + m] = unpk_add(acc1[m]);
    }
    __syncthreads();

    #pragma unroll
    for (int t = 0; t < 3; t++) {
        const int i2 = tid + t * 256;       // = cc*12 + m, cc in 0..63
        const int cc = i2 / 12, m = i2 - 12 * cc;
        float e2v = 0.f;
        #pragma unroll
        for (int kk = 0; kk < 8; kk++) e2v += part[kk * 771 + i2];
        const float sg = 1.f / (1.f + __expf(-e2v));
        g_ev[(size_t)(b * M + m) * C + ct * 64 + cc] = __expf(sg);
    }
}

// ---------------------------------------------------------------------------
// kOut: grid 96, 256 thr. att = mask(cov>0, ev); row-sum inverse folded into
// the AV epilogue. x column read directly into regs (32 coalesced LDG).
// ---------------------------------------------------------------------------
__global__ void __launch_bounds__(256) kOut(const float* __restrict__ x,
                                            float* __restrict__ out) {
    const int bm = blockIdx.x;
    __shared__ float att[C];     // 4 KB (UN-normalized masked exp)
    __shared__ float rinv[NN];

    const int tid = threadIdx.x;
    const int w = tid >> 5, lane = tid & 31;

    // issue x loads early (independent of att)
    const float* xp = x + (size_t)bm * (NN * D) + tid;
    float xv[NN];
    #pragma unroll
    for (int k = 0; k < NN; k++) xv[k] = __ldg(xp + k * D);

    const float4 cv4 = ((const float4*)(g_cov + (size_t)bm * C))[tid];
    const float4 ev4 = ((const float4*)(g_ev + (size_t)bm * C))[tid];
    float4 a;
    a.x = (cv4.x > 0.f) ? ev4.x : 0.f;
    a.y = (cv4.y > 0.f) ? ev4.y : 0.f;
    a.z = (cv4.z > 0.f) ? ev4.z : 0.f;
    a.w = (cv4.w > 0.f) ? ev4.w : 0.f;
    ((float4*)att)[tid] = a;
    __syncthreads();

    // row sums (4 rows per warp, interleaved reductions)
    {
        float v[4];
        #pragma unroll
        for (int r = 0; r < 4; r++) v[r] = att[(w * 4 + r) * NN + lane];
        #pragma unroll
        for (int off = 16; off; off >>= 1) {
            #pragma unroll
            for (int r = 0; r < 4; r++)
                v[r] += __shfl_xor_sync(0xffffffffu, v[r], off);
        }
        #pragma unroll
        for (int r = 0; r < 4; r++)
            if (lane == 0) rinv[w * 4 + r] = 1.f / v[r];
    }
    __syncthreads();

    ull xv2[16];
    #pragma unroll
    for (int kk = 0; kk < 16; kk++) xv2[kk] = pk2(xv[2 * kk], xv[2 * kk + 1]);

    float* ot = out + (size_t)bm * (NN * D);
    #pragma unroll 4
    for (int n = 0; n < NN; n++) {
        const ulonglong2* ar = (const ulonglong2*)(att + n * NN);
        ull a2 = 0ull;
        #pragma unroll
        for (int jj = 0; jj < 8; jj++) {
            const ulonglong2 bv = ar[jj];        // broadcast LDS.128
            a2 = ffma2(bv.x, xv2[2 * jj], a2);
            a2 = ffma2(bv.y, xv2[2 * jj + 1], a2);
        }
        ot[n * D + tid] = unpk_add(a2) * rinv[n];
    }
}

// ---------------------------------------------------------------------------
extern "C" void kernel_launch(void* const* d_in, const int* in_sizes, int n_in,
                              void* d_out, int out_size) {
    const float* x  = (const float*)d_in[0];
    const float* W1 = (const float*)d_in[1];
    const float* W2 = (const float*)d_in[2];
    float* out = (float*)d_out;

    const int smemSU  = 8448 * sizeof(float);                     // 33,792 B
    const int smemMid = (16384 + 6144 + 384) * sizeof(float);     // 91,648 B
    cudaFuncSetAttribute(kSU, cudaFuncAttributeMaxDynamicSharedMemorySize, smemSU);
    cudaFuncSetAttribute(kMid, cudaFuncAttributeMaxDynamicSharedMemorySize, smemMid);

    kSU<<<112, 256, smemSU>>>(x, W1);
    kMid<<<320, 256, smemMid>>>(x, W2);
    kOut<<<BM, 256>>>(x, out);
}

// round 12
// speedup vs baseline: 1.3117x; 1.3117x over previous
#include <cuda_runtime.h>
#include <math.h>

#define B 8
#define M 12
#define NN 32
#define D 256
#define C 1024      // N*N
#define CH 512      // C/R
#define BM 96
#define GRID 148

typedef unsigned long long ull;

// Scratch (allocation-free rule: device globals)
__device__ float g_S[BM * NN];     // row sums per bm
__device__ float g_U[NN * CH];     // [n][o] collapsed-GEMM1 weights
__device__ float g_cov[BM * C];    // centered cov (sign -> mask)
__device__ float g_ev[BM * C];     // exp(sigmoid(e2)), pre-mask
__device__ unsigned g_bcnt;        // barrier counter (returns to 0 each barrier)
__device__ volatile int g_bflag;   // barrier sense (0 -> 1 -> 0 per run)
__device__ float g_junkf;          // keeps W2 prefetch loads alive

// ---- packed f32x2 helpers -------------------------------------------------
__device__ __forceinline__ ull ffma2(ull a, ull b, ull c) {
    ull d_;
    asm("fma.rn.f32x2 %0, %1, %2, %3;" : "=l"(d_) : "l"(a), "l"(b), "l"(c));
    return d_;
}
__device__ __forceinline__ ull pk2(float lo, float hi) {
    ull r;
    asm("mov.b64 %0, {%1, %2};" : "=l"(r) : "f"(lo), "f"(hi));
    return r;
}
__device__ __forceinline__ float unpk_add(ull v) {
    float lo, hi;
    asm("mov.b64 {%0, %1}, %2;" : "=f"(lo), "=f"(hi) : "l"(v));
    return lo + hi;
}
__device__ __forceinline__ void unpk2(ull v, float& lo, float& hi) {
    asm("mov.b64 {%0, %1}, %2;" : "=f"(lo), "=f"(hi) : "l"(v));
}

// smem swizzle: q in [0,128) float4 units within a 512-float row
#define SWZ(q) (((q) & 0x70) | (((q) ^ ((q) >> 4)) & 0x0F))
#define SWZ4(o) (SWZ((o) >> 2) * 4 + ((o) & 3))
#define XPAD 260   // floats per padded x row (= 65 float4)

// Grid-wide sense-reversing barrier. Safe: grid == 148 == one full wave.
__device__ __forceinline__ void gbar(int sense) {
    __syncthreads();
    if (threadIdx.x == 0) {
        __threadfence();
        if (atomicAdd(&g_bcnt, 1) == GRID - 1) {
            g_bcnt = 0;
            __threadfence();
            g_bflag = sense;
        } else {
            while (g_bflag != sense) __nanosleep(32);
        }
        __threadfence();
    }
    __syncthreads();
}

// ---------------------------------------------------------------------------
__global__ void __launch_bounds__(256) kFused(const float* __restrict__ x,
                                              const float* __restrict__ W1,
                                              const float* __restrict__ W2,
                                              float* __restrict__ out) {
    extern __shared__ float sm[];
    const int bid = blockIdx.x;
    const int tid = threadIdx.x;
    const int w = tid >> 5, lane = tid & 31;

    // ======================= PHASE 1 =======================
    if (bid < BM) {
        // ---- per-bm: one x pass -> S + full 32x32 centered cov ----
        const int bm = bid;
        float* xs  = sm;             // padded natural [n*XPAD + d], 8320
        float* red = sm + 8320;      // 8 warps x 1024
        float* sp  = sm + 16512;     // 256
        float* S   = sm + 16768;     // 32

        const float4* xg4 = (const float4*)(x + (size_t)bm * (NN * D));
        float4* xs4 = (float4*)xs;
        #pragma unroll
        for (int t = 0; t < 8; t++) {
            const int i = tid + t * 256;
            const int n = i >> 6, q = i & 63;
            xs4[n * 65 + q] = xg4[i];    // conflict-free STS.128
        }
        __syncthreads();

        // xk = x[k=lane][w*32 .. w*32+31], packed pairs; also S partials
        ull xk2[16];
        float spv = 0.f;
        const float* xrow = xs + lane * XPAD + w * 32;
        #pragma unroll
        for (int j = 0; j < 16; j++) {
            const ull v = *(const ull*)(xrow + 2 * j);
            xk2[j] = v;
            float lo, hi; unpk2(v, lo, hi);
            spv += lo + hi;
        }
        sp[w * 32 + lane] = spv;
        __syncthreads();
        if (tid < 32) {
            float s = 0.f;
            #pragma unroll
            for (int ww = 0; ww < 8; ww++) s += sp[ww * 32 + tid];
            S[tid] = s;
            g_S[bm * NN + tid] = s;
        }
        __syncthreads();

        // cov partials: acc2[n] += x[n][d-pair] * xk[d-pair]
        ull acc2[32];
        #pragma unroll
        for (int n = 0; n < NN; n++) acc2[n] = 0ull;

        const ulonglong2* xs2 = (const ulonglong2*)xs;   // rows stride 65 f4
        #pragma unroll
        for (int n = 0; n < NN; n++) {
            const ulonglong2* rowp = xs2 + n * 65 + w * 8;
            #pragma unroll
            for (int jj = 0; jj < 8; jj++) {
                const ulonglong2 bv = rowp[jj];          // broadcast LDS.128
                acc2[n] = ffma2(bv.x, xk2[2 * jj], acc2[n]);
                acc2[n] = ffma2(bv.y, xk2[2 * jj + 1], acc2[n]);
            }
        }
        #pragma unroll
        for (int n = 0; n < NN; n++) red[w * 1024 + n * 32 + lane] = unpk_add(acc2[n]);
        __syncthreads();

        {   // combine 8 warp-partials, subtract S_n S_k / 256
            const float4* red4 = (const float4*)red;
            float4 cv = make_float4(0.f, 0.f, 0.f, 0.f);
            #pragma unroll
            for (int ww = 0; ww < 8; ww++) {
                const float4 t = red4[ww * 256 + tid];
                cv.x += t.x; cv.y += t.y; cv.z += t.z; cv.w += t.w;
            }
            const int n = tid >> 3, k0 = (tid & 7) * 4;
            const float sn = S[n] * (1.f / 256.f);
            cv.x -= sn * S[k0 + 0]; cv.y -= sn * S[k0 + 1];
            cv.z -= sn * S[k0 + 2]; cv.w -= sn * S[k0 + 3];
            ((float4*)(g_cov + (size_t)bm * C))[tid] = cv;
        }
    } else {
        // ---- U blocks (52): o-chunks of 10, then W2 L2-prefetch ----
        const int ub = bid - BM;
        float* smT = sm + w * 1056;   // per-warp 33x32 transpose buf

        #pragma unroll
        for (int r = 0; r < 2; r++) {
            const int i = r * 8 + w;
            if (i < 10) {
                const int o = ub * 10 + i;
                if (o < CH) {
                    const float* row = W1 + (size_t)o * C;
                    float rr[32], cs = 0.f;
                    #pragma unroll
                    for (int j = 0; j < 32; j++) { rr[j] = row[j * 32 + lane]; cs += rr[j]; }
                    #pragma unroll
                    for (int j = 0; j < 32; j++) smT[j * 33 + lane] = rr[j];
                    __syncwarp();
                    float rs = 0.f;
                    #pragma unroll
                    for (int mm = 0; mm < 32; mm++) rs += smT[lane * 33 + mm];
                    const float dg = smT[lane * 33 + lane];
                    g_U[lane * CH + o] = rs + 2.f * cs - dg;   // lane = n
                    __syncwarp();
                }
            }
        }

        // W2 prefetch into L2 (overlaps phase-1 compute elsewhere)
        const float4* w2g4 = (const float4*)W2;
        float s = 0.f;
        #pragma unroll
        for (int j = 0; j < 10; j++) {
            const int idx = ub * 256 + tid + j * 13312;
            if (idx < 131072) {
                const float4 v = w2g4[idx];
                s += (v.x + v.y) + (v.z + v.w);
            }
        }
        if (__float_as_uint(s) == 0xDEADBEEFu) g_junkf = s;  // never true; keeps loads
    }

    gbar(1);

    // ======================= PHASE 2: e2 (blocks 0..127) =======================
    if (bid < 128) {
        const int ct = bid >> 3, b = bid & 7;
        float* W2s  = sm;                    // 16384 floats (32-row pass)
        float* hs   = sm + 16384;            // 12 x 512 swizzled
        float* S12t = sm + 22528;            // [n*12 + m], 384

        const float4* w2g = (const float4*)(W2 + (size_t)(ct * 64) * CH);

        #pragma unroll
        for (int t = 0; t < 16; t++) {
            const int i = tid + t * 256;
            const int r = i >> 7, q = i & 127;
            ((float4*)W2s)[r * 128 + SWZ(q)] = w2g[i];
        }
        for (int i = tid; i < 384; i += 256) {
            const int m = i >> 5, n = i & 31;
            S12t[n * 12 + m] = g_S[(b * M + m) * NN + n];
        }
        __syncthreads();

        // h inline: thread owns o0 = tid, o1 = tid+256
        {
            ull hacc[12];
            #pragma unroll
            for (int mm = 0; mm < 12; mm++) hacc[mm] = 0ull;
            #pragma unroll 4
            for (int n = 0; n < 32; n++) {
                const float u0 = g_U[n * CH + tid];
                const float u1 = g_U[n * CH + tid + 256];
                const ull u00 = pk2(u0, u0), u11 = pk2(u1, u1);
                #pragma unroll
                for (int mm = 0; mm < 6; mm++) {
                    const ull sv = *(const ull*)(S12t + n * 12 + 2 * mm);
                    hacc[mm]     = ffma2(sv, u00, hacc[mm]);
                    hacc[6 + mm] = ffma2(sv, u11, hacc[6 + mm]);
                }
            }
            const int so0 = SWZ4(tid), so1 = SWZ4(tid + 256);
            #pragma unroll
            for (int mm = 0; mm < 6; mm++) {
                float a, bb;
                unpk2(hacc[mm], a, bb);
                hs[(2 * mm) * 512 + so0]     = fmaxf(a  * (1.f / 512.f), 0.f);
                hs[(2 * mm + 1) * 512 + so0] = fmaxf(bb * (1.f / 512.f), 0.f);
                unpk2(hacc[6 + mm], a, bb);
                hs[(2 * mm) * 512 + so1]     = fmaxf(a  * (1.f / 512.f), 0.f);
                hs[(2 * mm + 1) * 512 + so1] = fmaxf(bb * (1.f / 512.f), 0.f);
            }
        }
        __syncthreads();

        const int c2 = tid >> 3;          // row within pass (0..31)
        const int kc = tid & 7;           // k-chunk of 64 floats
        const int kc16 = kc * 16;
        const ulonglong2* hu = (const ulonglong2*)hs;
        const ulonglong2* Wu = (const ulonglong2*)W2s;

        ull acc0[12], acc1[12];
        #pragma unroll
        for (int m = 0; m < 12; m++) { acc0[m] = 0ull; acc1[m] = 0ull; }

        #pragma unroll 4
        for (int j = 0; j < 16; j++) {
            const int qs = kc16 + ((j ^ kc) & 15);
            const ulonglong2 wv = Wu[c2 * 128 + qs];
            #pragma unroll
            for (int m = 0; m < 12; m++) {
                const ulonglong2 hv = hu[m * 128 + qs];
                acc0[m] = ffma2(wv.x, hv.x, acc0[m]);
                acc0[m] = ffma2(wv.y, hv.y, acc0[m]);
            }
        }
        __syncthreads();
        #pragma unroll
        for (int t = 0; t < 16; t++) {
            const int i = tid + t * 256;
            const int r = i >> 7, q = i & 127;
            ((float4*)W2s)[r * 128 + SWZ(q)] = w2g[4096 + i];
        }
        __syncthreads();
        #pragma unroll 4
        for (int j = 0; j < 16; j++) {
            const int qs = kc16 + ((j ^ kc) & 15);
            const ulonglong2 wv = Wu[c2 * 128 + qs];
            #pragma unroll
            for (int m = 0; m < 12; m++) {
                const ulonglong2 hv = hu[m * 128 + qs];
                acc1[m] = ffma2(wv.x, hv.x, acc1[m]);
                acc1[m] = ffma2(wv.y, hv.y, acc1[m]);
            }
        }
        __syncthreads();   // done with W2s; reuse as partials

        float* part = W2s;   // [kc][row*12+m], stride 771
        #pragma unroll
        for (int m = 0; m < 12; m++) {
            part[kc * 771 + c2 * 12 + m]        = unpk_add(acc0[m]);
            part[kc * 771 + (32 + c2) * 12 + m] = unpk_add(acc1[m]);
        }
        __syncthreads();

        #pragma unroll
        for (int t = 0; t < 3; t++) {
            const int i2 = tid + t * 256;       // = cc*12 + m, cc in 0..63
            const int cc = i2 / 12, m = i2 - 12 * cc;
            float e2v = 0.f;
            #pragma unroll
            for (int kk = 0; kk < 8; kk++) e2v += part[kk * 771 + i2];
            const float sg = 1.f / (1.f + __expf(-e2v));
            g_ev[(size_t)(b * M + m) * C + ct * 64 + cc] = __expf(sg);
        }
    }

    gbar(0);

    // ======================= PHASE 3: out (blocks 0..95) =======================
    if (bid < BM) {
        const int bm = bid;
        float* att  = sm;          // 1024 (un-normalized masked exp)
        float* rinv = sm + 1024;   // 32

        // x column d=tid into regs (L2-warm after phase 1)
        const float* xp = x + (size_t)bm * (NN * D) + tid;
        float xv[NN];
        #pragma unroll
        for (int k = 0; k < NN; k++) xv[k] = __ldg(xp + k * D);

        const float4 cv4 = ((const float4*)(g_cov + (size_t)bm * C))[tid];
        const float4 ev4 = ((const float4*)(g_ev + (size_t)bm * C))[tid];
        float4 a;
        a.x = (cv4.x > 0.f) ? ev4.x : 0.f;
        a.y = (cv4.y > 0.f) ? ev4.y : 0.f;
        a.z = (cv4.z > 0.f) ? ev4.z : 0.f;
        a.w = (cv4.w > 0.f) ? ev4.w : 0.f;
        ((float4*)att)[tid] = a;
        __syncthreads();

        {   // row sums -> inverses (4 rows per warp, interleaved)
            float v[4];
            #pragma unroll
            for (int r = 0; r < 4; r++) v[r] = att[(w * 4 + r) * NN + lane];
            #pragma unroll
            for (int off = 16; off; off >>= 1) {
                #pragma unroll
                for (int r = 0; r < 4; r++)
                    v[r] += __shfl_xor_sync(0xffffffffu, v[r], off);
            }
            #pragma unroll
            for (int r = 0; r < 4; r++)
                if (lane == 0) rinv[w * 4 + r] = 1.f / v[r];
        }
        __syncthreads();

        ull xv2[16];
        #pragma unroll
        for (int kk = 0; kk < 16; kk++) xv2[kk] = pk2(xv[2 * kk], xv[2 * kk + 1]);

        float* ot = out + (size_t)bm * (NN * D);
        #pragma unroll 4
        for (int n = 0; n < NN; n++) {
            const ulonglong2* ar = (const ulonglong2*)(att + n * NN);
            ull a2 = 0ull;
            #pragma unroll
            for (int jj = 0; jj < 8; jj++) {
                const ulonglong2 bv = ar[jj];        // broadcast LDS.128
                a2 = ffma2(bv.x, xv2[2 * jj], a2);
                a2 = ffma2(bv.y, xv2[2 * jj + 1], a2);
            }
            ot[n * D + tid] = unpk_add(a2) * rinv[n];
        }
    }
}

// ---------------------------------------------------------------------------
extern "C" void kernel_launch(void* const* d_in, const int* in_sizes, int n_in,
                              void* d_out, int out_size) {
    const float* x  = (const float*)d_in[0];
    const float* W1 = (const float*)d_in[1];
    const float* W2 = (const float*)d_in[2];
    float* out = (float*)d_out;

    const int smem = 22912 * sizeof(float);   // 91,648 B (phase-2 high-water)
    cudaFuncSetAttribute(kFused, cudaFuncAttributeMaxDynamicSharedMemorySize, smem);

    kFused<<<GRID, 256, smem>>>(x, W1, W2, out);
}